// round 1
// baseline (speedup 1.0000x reference)
#include <cuda_runtime.h>
#include <cstdint>
#include <cstddef>

// Problem dims (fixed by the reference)
#define NB 64      // batch
#define NI 1024    // input capsules
#define DI 16      // input capsule dim
#define NJ 32      // output capsules
#define DJ 32      // output capsule dim
#define ROW 1024   // NJ*DJ, floats per (b,i) row of inputs_hat

// ---------------------------------------------------------------------------
// Scratch (static __device__ arrays — the sanctioned no-alloc workaround)
// ---------------------------------------------------------------------------
__device__ __align__(256) float g_hat[(size_t)NB * NI * ROW];   // 268 MB fp32
__device__ __align__(256) float g_bstate[NB * NI * NJ];         // routing logits b
__device__ __align__(256) float g_outs[3][NB * ROW];            // pre-squash outputs per iter
__device__ __align__(256) float g_v[NB * ROW];                  // squashed v between iters

// ---------------------------------------------------------------------------
// Packed f32x2 helpers (Blackwell: doubles fp32 FMA throughput)
// ---------------------------------------------------------------------------
__device__ __forceinline__ unsigned long long pack2(float a, float b) {
    unsigned long long r;
    asm("mov.b64 %0, {%1, %2};" : "=l"(r) : "f"(a), "f"(b));
    return r;
}
__device__ __forceinline__ unsigned long long fma2(unsigned long long a,
                                                   unsigned long long b,
                                                   unsigned long long c) {
    unsigned long long r;
    asm("fma.rn.f32x2 %0, %1, %2, %3;" : "=l"(r) : "l"(a), "l"(b), "l"(c));
    return r;
}
__device__ __forceinline__ void unpack2(unsigned long long v, float& a, float& b) {
    asm("mov.b64 {%0, %1}, %2;" : "=f"(a), "=f"(b) : "l"(v));
}

// ---------------------------------------------------------------------------
// Zero the three output accumulators (needed every replay: pass kernels atomicAdd)
// ---------------------------------------------------------------------------
__global__ void zero_kernel() {
    int t = blockIdx.x * blockDim.x + threadIdx.x;   // grid covers exactly 3*NB*ROW
    ((float*)g_outs)[t] = 0.0f;
}

// ---------------------------------------------------------------------------
// Gen kernel: inputs_hat[b,i,j,m] = sum_n W[i,j,n,m] * x[b,i,n]
// One block per i. Thread t owns (j = t>>3, m-quad q = t&7); keeps the W column
// W[i, j, 0..15, 4q..4q+3] in 32 packed-f32x2 registers and loops all 64 b.
// Stores are perfectly coalesced (thread t writes float4 at element t*4).
// ---------------------------------------------------------------------------
__global__ void __launch_bounds__(256, 2)
gen_kernel(const float* __restrict__ x, const float* __restrict__ W) {
    const int i = blockIdx.x;
    const int t = threadIdx.x;
    const int j = t >> 3;
    const int q = t & 7;

    // Load this thread's W slice: 16 x float4 (coalesced: 4 lines / warp instr)
    const float4* wp = reinterpret_cast<const float4*>(
        W + ((size_t)i * NJ + j) * (DI * DJ) + 4 * q);
    unsigned long long w01[DI], w23[DI];
#pragma unroll
    for (int n = 0; n < DI; n++) {
        float4 w4 = wp[n * (DJ / 4)];
        w01[n] = pack2(w4.x, w4.y);
        w23[n] = pack2(w4.z, w4.w);
    }

    // Stage x[:, i, :] (64x16 floats = 4 KB) in SMEM
    __shared__ float sx[NB * DI];
    for (int e = t; e < NB * DI; e += 256) {
        int b = e >> 4, n = e & 15;
        sx[e] = x[((size_t)b * NI + i) * DI + n];
    }
    __syncthreads();

    float4* hp = reinterpret_cast<float4*>(
        g_hat + (size_t)i * ROW + (size_t)(j * DJ + 4 * q));
    const size_t bstride4 = (size_t)NI * ROW / 4;   // float4 stride between batches

    for (int b = 0; b < NB; b++) {
        unsigned long long a01 = 0ull, a23 = 0ull;  // == {0.f,0.f}
#pragma unroll
        for (int n = 0; n < DI; n++) {
            float xv = sx[b * DI + n];               // broadcast LDS, conflict-free
            unsigned long long x2 = pack2(xv, xv);
            a01 = fma2(x2, w01[n], a01);
            a23 = fma2(x2, w23[n], a23);
        }
        float4 out;
        unpack2(a01, out.x, out.y);
        unpack2(a23, out.z, out.w);
        hp[(size_t)b * bstride4] = out;
    }
}

// ---------------------------------------------------------------------------
// Fused routing pass. MODE 0: c uniform (iter 0). MODE 1: a = <hat, v1>,
// write b-state, softmax(a). MODE 2: logits = b-state + <hat, v2>, softmax.
// All modes accumulate out[b,j,m] += c[b,i,j]*hat[b,i,j,m] over this block's
// 128 i's, then block-reduce and atomicAdd into g_outs[MODE].
//
// Block = (b, i-tile of 128). Warp w handles i = tile*128 + s*8 + w.
// Lane mapping: element e = (l + 32r)*4 + k  ->  j = (l>>3) + 4r, m = 4*(l&7)+k.
// So lane group g = l>>3 owns j = g+4r (r=0..7), quad q = l&7 owns 4 m's.
// m-reduction: shfl_xor {1,2,4}; j-softmax reduction: shfl_xor {8,16}.
// ---------------------------------------------------------------------------
template <int MODE>
__global__ void __launch_bounds__(256, 2)
pass_kernel() {
    const int bx = blockIdx.x;
    const int b = bx >> 3;
    const int tile = bx & 7;
    const int w = threadIdx.x >> 5;
    const int l = threadIdx.x & 31;
    const int g = l >> 3;
    const int q = l & 7;

    float4 v4[8];
    if (MODE >= 1) {
#pragma unroll
        for (int r = 0; r < 8; r++) {
            int j = g + 4 * r;
            v4[r] = *reinterpret_cast<const float4*>(
                g_v + ((size_t)b * NJ + j) * DJ + 4 * q);
        }
    }

    float4 acc[8];
#pragma unroll
    for (int r = 0; r < 8; r++) acc[r] = make_float4(0.f, 0.f, 0.f, 0.f);

    for (int s = 0; s < 16; s++) {
        const int i = tile * 128 + s * 8 + w;
        const float4* hp = reinterpret_cast<const float4*>(
            g_hat + ((size_t)b * NI + i) * ROW);
        float4 h[8];
#pragma unroll
        for (int r = 0; r < 8; r++) h[r] = hp[l + 32 * r];   // fully coalesced

        if (MODE == 0) {
            const float c = 0.03125f;  // softmax(0) over 32 = 1/32 exactly
#pragma unroll
            for (int r = 0; r < 8; r++) {
                acc[r].x = fmaf(c, h[r].x, acc[r].x);
                acc[r].y = fmaf(c, h[r].y, acc[r].y);
                acc[r].z = fmaf(c, h[r].z, acc[r].z);
                acc[r].w = fmaf(c, h[r].w, acc[r].w);
            }
        } else {
            // partial dot over this lane's 4 m's
            float p[8];
#pragma unroll
            for (int r = 0; r < 8; r++)
                p[r] = fmaf(h[r].x, v4[r].x,
                        fmaf(h[r].y, v4[r].y,
                          fmaf(h[r].z, v4[r].z, h[r].w * v4[r].w)));
            // reduce over the 8 q-lanes sharing each j
#pragma unroll
            for (int r = 0; r < 8; r++) {
                p[r] += __shfl_xor_sync(0xffffffffu, p[r], 1);
                p[r] += __shfl_xor_sync(0xffffffffu, p[r], 2);
                p[r] += __shfl_xor_sync(0xffffffffu, p[r], 4);
            }
            if (MODE == 2) {
#pragma unroll
                for (int r = 0; r < 8; r++)
                    p[r] += g_bstate[((size_t)b * NI + i) * NJ + g + 4 * r];
            }
            if (MODE == 1) {
                if (q == 0) {
#pragma unroll
                    for (int r = 0; r < 8; r++)
                        g_bstate[((size_t)b * NI + i) * NJ + g + 4 * r] = p[r];
                }
            }
            // softmax over all 32 j (8 local + cross-group via xor 8,16)
            float mx = p[0];
#pragma unroll
            for (int r = 1; r < 8; r++) mx = fmaxf(mx, p[r]);
            mx = fmaxf(mx, __shfl_xor_sync(0xffffffffu, mx, 8));
            mx = fmaxf(mx, __shfl_xor_sync(0xffffffffu, mx, 16));
            float e[8], sum = 0.f;
#pragma unroll
            for (int r = 0; r < 8; r++) { e[r] = __expf(p[r] - mx); sum += e[r]; }
            sum += __shfl_xor_sync(0xffffffffu, sum, 8);
            sum += __shfl_xor_sync(0xffffffffu, sum, 16);
            const float inv = 1.0f / sum;
#pragma unroll
            for (int r = 0; r < 8; r++) {
                const float c = e[r] * inv;
                acc[r].x = fmaf(c, h[r].x, acc[r].x);
                acc[r].y = fmaf(c, h[r].y, acc[r].y);
                acc[r].z = fmaf(c, h[r].z, acc[r].z);
                acc[r].w = fmaf(c, h[r].w, acc[r].w);
            }
        }
    }

    // Block reduction: 8 warp copies in SMEM -> 1, then atomicAdd (few atomics)
    __shared__ float red[8][ROW];   // 32 KB
#pragma unroll
    for (int r = 0; r < 8; r++)
        *reinterpret_cast<float4*>(&red[w][(g + 4 * r) * DJ + 4 * q]) = acc[r];
    __syncthreads();
    for (int e = threadIdx.x; e < ROW; e += 256) {
        float sv = red[0][e];
#pragma unroll
        for (int ww = 1; ww < 8; ww++) sv += red[ww][e];
        atomicAdd(&g_outs[MODE][(size_t)b * ROW + e], sv);
    }
}

// ---------------------------------------------------------------------------
// Squash: v = (||s||^2/(1+||s||^2)) * s/sqrt(||s||^2 + 1e-7)
// Block = b, 1024 threads; warp == one j (lanes = m), shuffle reduction.
// ---------------------------------------------------------------------------
__global__ void squash_kernel(int srcIdx, float* __restrict__ dst) {
    const int b = blockIdx.x;
    const int t = threadIdx.x;
    const float s = g_outs[srcIdx][(size_t)b * ROW + t];
    float ss = s * s;
#pragma unroll
    for (int m = 16; m; m >>= 1) ss += __shfl_xor_sync(0xffffffffu, ss, m);
    const float scale = ss / ((1.0f + ss) * sqrtf(ss + 1e-7f));
    dst[(size_t)b * ROW + t] = scale * s;
}

// ---------------------------------------------------------------------------
// Launch: zero -> gen -> [pass0, squash->v] -> [pass1, squash->v] -> [pass2, squash->out]
// All async kernel launches on the default stream; graph-capturable, alloc-free.
// ---------------------------------------------------------------------------
extern "C" void kernel_launch(void* const* d_in, const int* in_sizes, int n_in,
                              void* d_out, int out_size) {
    (void)in_sizes; (void)n_in; (void)out_size;
    const float* x = (const float*)d_in[0];   // inputs [64,1024,16] fp32
    const float* W = (const float*)d_in[1];   // W [1024,32,16,32] fp32
    float* out = (float*)d_out;               // [64,32,32] fp32

    float* vptr = nullptr;
    cudaGetSymbolAddress((void**)&vptr, g_v);

    zero_kernel<<<(3 * NB * ROW) / 256, 256>>>();
    gen_kernel<<<NI, 256>>>(x, W);

    pass_kernel<0><<<NB * 8, 256>>>();
    squash_kernel<<<NB, ROW>>>(0, vptr);

    pass_kernel<1><<<NB * 8, 256>>>();
    squash_kernel<<<NB, ROW>>>(1, vptr);

    pass_kernel<2><<<NB * 8, 256>>>();
    squash_kernel<<<NB, ROW>>>(2, out);
}

// round 3
// speedup vs baseline: 1.3711x; 1.3711x over previous
#include <cuda_runtime.h>
#include <cuda_fp16.h>
#include <cstdint>
#include <cstddef>

// Problem dims (fixed by the reference)
#define NB 64      // batch
#define NI 1024    // input capsules
#define DI 16      // input capsule dim
#define NJ 32      // output capsules
#define DJ 32      // output capsule dim
#define ROW 1024   // NJ*DJ, floats per (b,i) row of inputs_hat

// ---------------------------------------------------------------------------
// Scratch (static __device__ arrays — the sanctioned no-alloc workaround)
// ---------------------------------------------------------------------------
__device__ __align__(256) __half g_hat[(size_t)NB * NI * ROW];  // 134 MB fp16
__device__ __align__(256) float g_bstate[NB * NI * NJ];         // routing logits b
__device__ __align__(256) float g_outs[3][NB * ROW];            // pre-squash outputs per iter

// ---------------------------------------------------------------------------
// Packed f32x2 helpers (Blackwell: doubles fp32 FMA throughput)
// ---------------------------------------------------------------------------
__device__ __forceinline__ unsigned long long pack2(float a, float b) {
    unsigned long long r;
    asm("mov.b64 %0, {%1, %2};" : "=l"(r) : "f"(a), "f"(b));
    return r;
}
__device__ __forceinline__ unsigned long long fma2(unsigned long long a,
                                                   unsigned long long b,
                                                   unsigned long long c) {
    unsigned long long r;
    asm("fma.rn.f32x2 %0, %1, %2, %3;" : "=l"(r) : "l"(a), "l"(b), "l"(c));
    return r;
}
__device__ __forceinline__ void unpack2(unsigned long long v, float& a, float& b) {
    asm("mov.b64 {%0, %1}, %2;" : "=f"(a), "=f"(b) : "l"(v));
}

// ---------------------------------------------------------------------------
// Zero the three output accumulators (needed every replay: pass kernels atomicAdd)
// ---------------------------------------------------------------------------
__global__ void zero_kernel() {
    int t = blockIdx.x * blockDim.x + threadIdx.x;   // grid covers exactly 3*NB*ROW
    ((float*)g_outs)[t] = 0.0f;
}

// ---------------------------------------------------------------------------
// Gen kernel: inputs_hat[b,i,j,m] = sum_n W[i,j,n,m] * x[b,i,n]  (fp16 store)
// One block per i. Thread t owns (j = t>>3, m-quad q = t&7); keeps the W column
// W[i, j, 0..15, 4q..4q+3] in 32 packed-f32x2 registers and loops all 64 b.
// x is staged pre-duplicated ((x,x) pairs) so the inner loop is LDS.64 + 2 FFMA2.
// ---------------------------------------------------------------------------
__global__ void __launch_bounds__(256, 2)
gen_kernel(const float* __restrict__ x, const float* __restrict__ W) {
    const int i = blockIdx.x;
    const int t = threadIdx.x;
    const int j = t >> 3;
    const int q = t & 7;

    // Load this thread's W slice: 16 x float4 (coalesced: 4 lines / warp instr)
    const float4* wp = reinterpret_cast<const float4*>(
        W + ((size_t)i * NJ + j) * (DI * DJ) + 4 * q);
    unsigned long long w01[DI], w23[DI];
#pragma unroll
    for (int n = 0; n < DI; n++) {
        float4 w4 = wp[n * (DJ / 4)];
        w01[n] = pack2(w4.x, w4.y);
        w23[n] = pack2(w4.z, w4.w);
    }

    // Stage x[:, i, :] duplicated as (x,x) 8-byte pairs (8 KB SMEM)
    __shared__ unsigned long long sx2[NB * DI];
    for (int e = t; e < NB * DI; e += 256) {
        int b = e >> 4, n = e & 15;
        float xv = x[((size_t)b * NI + i) * DI + n];
        sx2[e] = pack2(xv, xv);
    }
    __syncthreads();

    uint2* hp = reinterpret_cast<uint2*>(
        g_hat + (size_t)i * ROW + (size_t)(j * DJ + 4 * q));
    const size_t bstrideU2 = (size_t)NI * ROW / 4;   // uint2 stride between batches

    for (int b = 0; b < NB; b++) {
        unsigned long long a01 = 0ull, a23 = 0ull;  // == {0.f,0.f}
#pragma unroll
        for (int n = 0; n < DI; n++) {
            unsigned long long x2 = sx2[b * DI + n];  // LDS.64 broadcast
            a01 = fma2(x2, w01[n], a01);
            a23 = fma2(x2, w23[n], a23);
        }
        float ox, oy, oz, ow;
        unpack2(a01, ox, oy);
        unpack2(a23, oz, ow);
        union { uint2 u; __half2 h[2]; } cv;
        cv.h[0] = __floats2half2_rn(ox, oy);
        cv.h[1] = __floats2half2_rn(oz, ow);
        hp[(size_t)b * bstrideU2] = cv.u;            // STG.64, fully coalesced
    }
}

// ---------------------------------------------------------------------------
// Fused routing pass. MODE 0: c uniform (iter 0). MODE 1: a = <hat, v1>,
// write b-state, softmax(a). MODE 2: logits = b-state + <hat, v2>, softmax.
// MODE>=1 first recomputes v[b] = squash(g_outs[MODE-1][b]) into SMEM (fused
// squash — kills the standalone squash launches). All modes accumulate
// out[b,j,m] += c[b,i,j]*hat[b,i,j,m] over the block's 128 i's, then
// block-reduce and atomicAdd into g_outs[MODE].
//
// Block = (b, i-tile of 128). Warp w handles i = tile*128 + s*8 + w.
// Lane mapping: element e = (l + 32r)*4 + k  ->  j = (l>>3) + 4r, m = 4*(l&7)+k.
// m-reduction: shfl_xor {1,2,4}; j-softmax reduction: shfl_xor {8,16}.
// ---------------------------------------------------------------------------
template <int MODE>
__global__ void __launch_bounds__(256, 2)
pass_kernel() {
    const int bx = blockIdx.x;
    const int b = bx >> 3;
    const int tile = bx & 7;
    const int w = threadIdx.x >> 5;
    const int l = threadIdx.x & 31;
    const int g = l >> 3;
    const int q = l & 7;

    __shared__ float sv[ROW];   // squashed v for this b (4 KB)
    float4 v4[8];
    if (MODE >= 1) {
        // Fused squash of previous iteration's accumulated output.
        const int tj = threadIdx.x >> 3, tq = threadIdx.x & 7;
        float4 s4 = *reinterpret_cast<const float4*>(
            &g_outs[MODE - 1][(size_t)b * ROW + tj * DJ + 4 * tq]);
        float ss = s4.x * s4.x + s4.y * s4.y + s4.z * s4.z + s4.w * s4.w;
        ss += __shfl_xor_sync(0xffffffffu, ss, 1);
        ss += __shfl_xor_sync(0xffffffffu, ss, 2);
        ss += __shfl_xor_sync(0xffffffffu, ss, 4);
        const float sc = ss / ((1.0f + ss) * sqrtf(ss + 1e-7f));
        *reinterpret_cast<float4*>(&sv[tj * DJ + 4 * tq]) =
            make_float4(sc * s4.x, sc * s4.y, sc * s4.z, sc * s4.w);
        __syncthreads();
#pragma unroll
        for (int r = 0; r < 8; r++)
            v4[r] = *reinterpret_cast<const float4*>(&sv[(g + 4 * r) * DJ + 4 * q]);
    }

    float4 acc[8];
#pragma unroll
    for (int r = 0; r < 8; r++) acc[r] = make_float4(0.f, 0.f, 0.f, 0.f);

    for (int s = 0; s < 16; s++) {
        const int i = tile * 128 + s * 8 + w;
        const uint2* hp = reinterpret_cast<const uint2*>(
            g_hat + ((size_t)b * NI + i) * ROW);
        float4 h[8];
#pragma unroll
        for (int r = 0; r < 8; r++) {                 // LDG.64, fully coalesced
            union { uint2 u; __half2 hh[2]; } cv;
            cv.u = hp[l + 32 * r];
            float2 f01 = __half22float2(cv.hh[0]);
            float2 f23 = __half22float2(cv.hh[1]);
            h[r] = make_float4(f01.x, f01.y, f23.x, f23.y);
        }

        if (MODE == 0) {
            const float c = 0.03125f;  // softmax(0) over 32 = 1/32 exactly
#pragma unroll
            for (int r = 0; r < 8; r++) {
                acc[r].x = fmaf(c, h[r].x, acc[r].x);
                acc[r].y = fmaf(c, h[r].y, acc[r].y);
                acc[r].z = fmaf(c, h[r].z, acc[r].z);
                acc[r].w = fmaf(c, h[r].w, acc[r].w);
            }
        } else {
            // partial dot over this lane's 4 m's
            float p[8];
#pragma unroll
            for (int r = 0; r < 8; r++)
                p[r] = fmaf(h[r].x, v4[r].x,
                        fmaf(h[r].y, v4[r].y,
                          fmaf(h[r].z, v4[r].z, h[r].w * v4[r].w)));
            // reduce over the 8 q-lanes sharing each j
#pragma unroll
            for (int r = 0; r < 8; r++) {
                p[r] += __shfl_xor_sync(0xffffffffu, p[r], 1);
                p[r] += __shfl_xor_sync(0xffffffffu, p[r], 2);
                p[r] += __shfl_xor_sync(0xffffffffu, p[r], 4);
            }
            if (MODE == 2) {
#pragma unroll
                for (int r = 0; r < 8; r++)
                    p[r] += g_bstate[((size_t)b * NI + i) * NJ + g + 4 * r];
            }
            if (MODE == 1) {
                if (q == 0) {
#pragma unroll
                    for (int r = 0; r < 8; r++)
                        g_bstate[((size_t)b * NI + i) * NJ + g + 4 * r] = p[r];
                }
            }
            // softmax over all 32 j (8 local + cross-group via xor 8,16)
            float mx = p[0];
#pragma unroll
            for (int r = 1; r < 8; r++) mx = fmaxf(mx, p[r]);
            mx = fmaxf(mx, __shfl_xor_sync(0xffffffffu, mx, 8));
            mx = fmaxf(mx, __shfl_xor_sync(0xffffffffu, mx, 16));
            float e[8], sum = 0.f;
#pragma unroll
            for (int r = 0; r < 8; r++) { e[r] = __expf(p[r] - mx); sum += e[r]; }
            sum += __shfl_xor_sync(0xffffffffu, sum, 8);
            sum += __shfl_xor_sync(0xffffffffu, sum, 16);
            const float inv = 1.0f / sum;
#pragma unroll
            for (int r = 0; r < 8; r++) {
                const float c = e[r] * inv;
                acc[r].x = fmaf(c, h[r].x, acc[r].x);
                acc[r].y = fmaf(c, h[r].y, acc[r].y);
                acc[r].z = fmaf(c, h[r].z, acc[r].z);
                acc[r].w = fmaf(c, h[r].w, acc[r].w);
            }
        }
    }

    // Block reduction: 8 warp copies in SMEM -> 1, then atomicAdd (few atomics)
    __shared__ float red[8][ROW];   // 32 KB
#pragma unroll
    for (int r = 0; r < 8; r++)
        *reinterpret_cast<float4*>(&red[w][(g + 4 * r) * DJ + 4 * q]) = acc[r];
    __syncthreads();
    for (int e = threadIdx.x; e < ROW; e += 256) {
        float sval = red[0][e];
#pragma unroll
        for (int ww = 1; ww < 8; ww++) sval += red[ww][e];
        atomicAdd(&g_outs[MODE][(size_t)b * ROW + e], sval);
    }
}

// ---------------------------------------------------------------------------
// Final squash: v = (||s||^2/(1+||s||^2)) * s/sqrt(||s||^2 + 1e-7) -> d_out
// Block = b, 1024 threads; warp == one j (lanes = m), shuffle reduction.
// ---------------------------------------------------------------------------
__global__ void squash_final_kernel(float* __restrict__ dst) {
    const int b = blockIdx.x;
    const int t = threadIdx.x;
    const float s = g_outs[2][(size_t)b * ROW + t];
    float ss = s * s;
#pragma unroll
    for (int m = 16; m; m >>= 1) ss += __shfl_xor_sync(0xffffffffu, ss, m);
    const float scale = ss / ((1.0f + ss) * sqrtf(ss + 1e-7f));
    dst[(size_t)b * ROW + t] = scale * s;
}

// ---------------------------------------------------------------------------
// Launch: zero -> gen -> pass0 -> pass1 -> pass2 -> squash_final (6 launches)
// All async kernel launches on the default stream; graph-capturable, alloc-free.
// ---------------------------------------------------------------------------
extern "C" void kernel_launch(void* const* d_in, const int* in_sizes, int n_in,
                              void* d_out, int out_size) {
    (void)in_sizes; (void)n_in; (void)out_size;
    const float* x = (const float*)d_in[0];   // inputs [64,1024,16] fp32
    const float* W = (const float*)d_in[1];   // W [1024,32,16,32] fp32
    float* out = (float*)d_out;               // [64,32,32] fp32

    zero_kernel<<<(3 * NB * ROW) / 256, 256>>>();
    gen_kernel<<<NI, 256>>>(x, W);

    pass_kernel<0><<<NB * 8, 256>>>();
    pass_kernel<1><<<NB * 8, 256>>>();
    pass_kernel<2><<<NB * 8, 256>>>();

    squash_final_kernel<<<NB, ROW>>>(out);
}